// round 7
// baseline (speedup 1.0000x reference)
#include <cuda_runtime.h>
#include <math.h>

#define N_ELEMS 16384
#define NBINS   4096
#define NCTA    16
#define TPB     1024
#define DELTA_F 0.1f
#define EPS_F   1e-12f
#define FIX_SCALE 4294967296.0         // 2^32

// ---- scratch (__device__ globals; zero-initialized at load) ----------------
__device__ float d_sorted[N_ELEMS];
__device__ int   d_hist[NBINS];               // invariant: zero at launch entry
__device__ int   d_rank[NBINS];               // invariant: zero at launch entry
__device__ unsigned long long d_accum;        // invariant: zero at launch entry
__device__ int   d_done;                      // invariant: zero at launch entry
__device__ volatile int d_sense;
__device__ int   d_barcnt;

__device__ __forceinline__ int warp_iscan(int v) {
#pragma unroll
    for (int o = 1; o < 32; o <<= 1) {
        int n = __shfl_up_sync(0xffffffffu, v, o);
        if ((threadIdx.x & 31) >= o) v += n;
    }
    return v;
}

__global__ __launch_bounds__(TPB)
void ghm_fused(const float* __restrict__ logits,
               const float* __restrict__ targets,
               float* __restrict__ out) {
    const int t   = threadIdx.x;
    const int bid = blockIdx.x;
    const int i   = bid * TPB + t;     // this thread owns element i throughout

    __shared__ int s_pref[NBINS + 4];  // full exclusive prefix (int4-aligned pad)
    __shared__ int s_wsum[32];
    __shared__ unsigned long long s_acc[32];

    int ls = d_sense;

    // ---- P0: prep g + global histogram ----
    float x  = logits[i];
    float tv = targets[i];
    float pred = 1.0f / (1.0f + expf(-x));
    float g    = fabsf(pred - tv);
    int   myb  = min((int)(g * (float)NBINS), NBINS - 1);
    atomicAdd(&d_hist[myb], 1);

    // ---- B1 arrive (CG sync_grids pattern, split) ----
    __syncthreads();
    int arr = -1;
    if (t == 0) { __threadfence(); arr = atomicAdd(&d_barcnt, 1); }

    // overlapped with barrier latency: loss (needed only in P4)
    float loss = fmaxf(x, 0.0f) - x * tv + log1pf(expf(-fabsf(x)));

    // ---- B1 wait ----
    if (t == 0) {
        if (arr == NCTA - 1) { d_barcnt = 0; __threadfence(); d_sense = 1 - ls; }
        else { while (d_sense == ls) { } __threadfence(); }
    }
    ls = 1 - ls;
    __syncthreads();

    // ---- P1: full exclusive prefix of d_hist into this CTA's smem ----
    {
        int4 hv = ((const int4*)d_hist)[t];          // bins 4t..4t+3
        int tot = hv.x + hv.y + hv.z + hv.w;
        int incl = warp_iscan(tot);
        if ((t & 31) == 31) s_wsum[t >> 5] = incl;
        __syncthreads();
        if (t < 32) s_wsum[t] = warp_iscan(s_wsum[t]);
        __syncthreads();
        int base = incl - tot + ((t >> 5) ? s_wsum[(t >> 5) - 1] : 0);
        int4 pr;
        pr.x = base;
        pr.y = base + hv.x;
        pr.z = pr.y + hv.y;
        pr.w = pr.z + hv.z;
        ((int4*)s_pref)[t] = pr;
        if (t == TPB - 1) s_pref[NBINS] = N_ELEMS;
    }
    __syncthreads();

    // ---- P2: scatter (d_rank starts 0; atomics commute -> no extra barrier)
    {
        int pos = s_pref[myb] + atomicAdd(&d_rank[myb], 1);
        d_sorted[pos] = g;
    }

    // ---- B2: all scatters complete ----
    __syncthreads();
    if (t == 0) {
        __threadfence();
        arr = atomicAdd(&d_barcnt, 1);
        if (arr == NCTA - 1) { d_barcnt = 0; __threadfence(); d_sense = 1 - ls; }
        else { while (d_sense == ls) { } __threadfence(); }
    }
    ls = 1 - ls;
    __syncthreads();

    // restore zero-invariants (hist & rank fully consumed; overlaps query)
    if (t < NBINS / NCTA) {            // 256 bins per CTA
        d_hist[bid * (NBINS / NCTA) + t] = 0;
        d_rank[bid * (NBINS / NCTA) + t] = 0;
    }

    // ---- P3: range-count query ----
    // Interior bins [loBin+3, hiBin-3] guaranteed all-pass (>=1 bin-width
    // margin vs fp32 compare fuzz); bins outside [loBin-2, hiBin+2] guaranteed
    // all-fail; edge windows checked with the reference's exact fp32 compare.
    unsigned long long fixterm;
    {
        float p = g * (float)NBINS;
        int loBin = (int)floorf(p - 0.1f * (float)NBINS);
        int hiBin = (int)floorf(p + 0.1f * (float)NBINS);

        int iLo = min(max(loBin + 3, 0), NBINS);
        int iHi = min(max(hiBin - 2, 0), NBINS);
        int cnt = (iHi > iLo) ? (s_pref[iHi] - s_pref[iLo]) : 0;

        // lower edge window: bins [loBin-2, loBin+2] -> contiguous element run
        {
            int a0 = max(loBin - 2, 0), b0 = min(loBin + 2, NBINS - 1);
            if (b0 >= a0) {
                int s = s_pref[a0], e = s_pref[b0 + 1];
#pragma unroll 4
                for (int idx = s; idx < e; idx++)
                    cnt += (fabsf(d_sorted[idx] - g) <= DELTA_F) ? 1 : 0;
            }
        }
        // upper edge window: bins [hiBin-2, hiBin+2]
        {
            int a1 = max(hiBin - 2, 0), b1 = min(hiBin + 2, NBINS - 1);
            if (b1 >= a1) {
                int s = s_pref[a1], e = s_pref[b1 + 1];
#pragma unroll 4
                for (int idx = s; idx < e; idx++)
                    cnt += (fabsf(d_sorted[idx] - g) <= DELTA_F) ? 1 : 0;
            }
        }

        float GD   = (float)cnt / DELTA_F;
        float beta = (float)N_ELEMS / (GD + EPS_F);
        float term = beta * loss;      // >= 0
        fixterm = (unsigned long long)((double)term * FIX_SCALE);
    }

    // ---- P4: deterministic finalize (u64 fixed-point; shuffle reduce) ----
    {
        unsigned long long v = fixterm;
#pragma unroll
        for (int off = 16; off > 0; off >>= 1)
            v += __shfl_down_sync(0xffffffffu, v, off);
        if ((t & 31) == 0) s_acc[t >> 5] = v;
        __syncthreads();
        if (t < 32) {
            unsigned long long w = s_acc[t];
#pragma unroll
            for (int off = 16; off > 0; off >>= 1)
                w += __shfl_down_sync(0xffffffffu, w, off);
            if (t == 0) {
                atomicAdd(&d_accum, w);
                __threadfence();
                if (atomicAdd(&d_done, 1) == NCTA - 1) {
                    __threadfence();
                    unsigned long long total = atomicAdd(&d_accum, 0ULL);
                    out[0] = (float)(((double)total / FIX_SCALE) / (double)N_ELEMS);
                    d_accum = 0ULL;    // restore invariants for next replay
                    d_done  = 0;
                    __threadfence();
                }
            }
        }
    }
}

// ---------------------------------------------------------------------------
extern "C" void kernel_launch(void* const* d_in, const int* in_sizes, int n_in,
                              void* d_out, int out_size) {
    const float* logits  = (const float*)d_in[0];
    const float* targets = (const float*)d_in[1];
    float* out = (float*)d_out;

    ghm_fused<<<NCTA, TPB>>>(logits, targets, out);
}

// round 8
// speedup vs baseline: 1.4877x; 1.4877x over previous
#include <cuda_runtime.h>
#include <math.h>

#define N_ELEMS 16384
#define NBINS   4096
#define NCTA    64
#define TPB     256
#define BPT     (NBINS / TPB)          // 16 bins per thread
#define DELTA_F 0.1f
#define EPS_F   1e-12f
#define FIX_SCALE 4294967296.0         // 2^32

// Dynamic smem layout: [0, 16400) s_pref ints, [16640, 16640+65536) s_sorted
#define SMEM_PREF_BYTES  ((NBINS + 4) * 4)
#define SMEM_SORT_OFF    16640          // 128B-aligned
#define SMEM_TOTAL_BYTES (SMEM_SORT_OFF + N_ELEMS * 4)

// ---- scratch (__device__ globals; zero-initialized at load) ----------------
__device__ float d_sorted[N_ELEMS];
__device__ int   d_hist[NBINS];               // invariant: zero at launch entry
__device__ int   d_rank[NBINS];               // invariant: zero at launch entry
__device__ unsigned long long d_accum;        // invariant: zero at launch entry
__device__ int   d_done;                      // invariant: zero at launch entry
__device__ volatile int d_sense;
__device__ int   d_barcnt;

__device__ __forceinline__ int warp_iscan(int v) {
#pragma unroll
    for (int o = 1; o < 32; o <<= 1) {
        int n = __shfl_up_sync(0xffffffffu, v, o);
        if ((threadIdx.x & 31) >= o) v += n;
    }
    return v;
}

__global__ __launch_bounds__(TPB)
void ghm_fused(const float* __restrict__ logits,
               const float* __restrict__ targets,
               float* __restrict__ out) {
    extern __shared__ char smem[];
    int*   s_pref   = (int*)smem;                       // NBINS+1 entries
    float* s_sorted = (float*)(smem + SMEM_SORT_OFF);   // N_ELEMS entries
    __shared__ int s_wsum[8];
    __shared__ unsigned long long s_acc[8];

    const int t   = threadIdx.x;
    const int bid = blockIdx.x;
    const int i   = bid * TPB + t;     // this thread owns element i throughout

    int ls = d_sense;

    // ---- P0: prep g + global histogram ----
    float x  = logits[i];
    float tv = targets[i];
    float pred = 1.0f / (1.0f + __expf(-x));
    float g    = fabsf(pred - tv);
    int   myb  = min((int)(g * (float)NBINS), NBINS - 1);
    atomicAdd(&d_hist[myb], 1);

    // ---- B1 arrive (split: loss hoisted into barrier shadow) ----
    __syncthreads();
    int arr = -1;
    if (t == 0) { __threadfence(); arr = atomicAdd(&d_barcnt, 1); }

    float loss = fmaxf(x, 0.0f) - x * tv + log1pf(__expf(-fabsf(x)));

    // ---- B1 wait ----
    if (t == 0) {
        if (arr == NCTA - 1) { d_barcnt = 0; __threadfence(); d_sense = 1 - ls; }
        else { while (d_sense == ls) { } __threadfence(); }
    }
    ls = 1 - ls;
    __syncthreads();

    // ---- P1: full exclusive prefix of d_hist into this CTA's smem ----
    {
        int h[BPT];
        const int4* hv = (const int4*)&d_hist[t * BPT];
        int4 a = hv[0], b = hv[1], c = hv[2], d = hv[3];
        h[0]=a.x; h[1]=a.y; h[2]=a.z; h[3]=a.w;
        h[4]=b.x; h[5]=b.y; h[6]=b.z; h[7]=b.w;
        h[8]=c.x; h[9]=c.y; h[10]=c.z; h[11]=c.w;
        h[12]=d.x; h[13]=d.y; h[14]=d.z; h[15]=d.w;
        int tot = 0;
#pragma unroll
        for (int k = 0; k < BPT; k++) tot += h[k];
        int incl = warp_iscan(tot);
        if ((t & 31) == 31) s_wsum[t >> 5] = incl;
        __syncthreads();
        if (t < 8) {
            int w = s_wsum[t];
#pragma unroll
            for (int o = 1; o < 8; o <<= 1) {
                int n = __shfl_up_sync(0xffu, w, o);
                if (t >= o) w += n;
            }
            s_wsum[t] = w;
        }
        __syncthreads();
        int base = incl - tot + ((t >> 5) ? s_wsum[(t >> 5) - 1] : 0);
#pragma unroll
        for (int k = 0; k < BPT; k++) {
            s_pref[t * BPT + k] = base;
            base += h[k];
        }
        if (t == TPB - 1) s_pref[NBINS] = N_ELEMS;
    }
    __syncthreads();

    // ---- P2: scatter (d_rank starts 0; atomics commute -> no extra barrier)
    {
        int pos = s_pref[myb] + atomicAdd(&d_rank[myb], 1);
        d_sorted[pos] = g;
    }

    // ---- B2: all scatters complete ----
    __syncthreads();
    if (t == 0) {
        __threadfence();
        arr = atomicAdd(&d_barcnt, 1);
        if (arr == NCTA - 1) { d_barcnt = 0; __threadfence(); d_sense = 1 - ls; }
        else { while (d_sense == ls) { } __threadfence(); }
    }
    ls = 1 - ls;
    __syncthreads();

    // restore zero-invariants (hist & rank fully consumed by now)
    if (t < NBINS / NCTA) {            // 64 bins per CTA
        d_hist[bid * (NBINS / NCTA) + t] = 0;
        d_rank[bid * (NBINS / NCTA) + t] = 0;
    }

    // stage full sorted array into this CTA's smem (16 x LDG.128 per thread)
    {
        const float4* src = (const float4*)d_sorted;
        float4*       dst = (float4*)s_sorted;
#pragma unroll
        for (int k = 0; k < N_ELEMS / 4 / TPB; k++)     // 16 iters
            dst[k * TPB + t] = src[k * TPB + t];
    }
    __syncthreads();

    // ---- P3: range-count query (interior via prefix diff, edges exact) ----
    // Interior bins [loBin+3, hiBin-3] guaranteed all-pass (>=1 bin-width
    // margin vs fp32 compare fuzz); bins outside [loBin-2, hiBin+2] guaranteed
    // all-fail; edge windows checked with the reference's exact fp32 compare.
    unsigned long long fixterm;
    {
        float p = g * (float)NBINS;
        int loBin = (int)floorf(p - 0.1f * (float)NBINS);
        int hiBin = (int)floorf(p + 0.1f * (float)NBINS);

        int iLo = min(max(loBin + 3, 0), NBINS);
        int iHi = min(max(hiBin - 2, 0), NBINS);
        int cnt = (iHi > iLo) ? (s_pref[iHi] - s_pref[iLo]) : 0;

        // lower edge window: bins [loBin-2, loBin+2] -> contiguous run in s_sorted
        {
            int a0 = max(loBin - 2, 0), b0 = min(loBin + 2, NBINS - 1);
            if (b0 >= a0) {
                int s = s_pref[a0], e = s_pref[b0 + 1];
#pragma unroll 8
                for (int idx = s; idx < e; idx++)
                    cnt += (fabsf(s_sorted[idx] - g) <= DELTA_F) ? 1 : 0;
            }
        }
        // upper edge window: bins [hiBin-2, hiBin+2]
        {
            int a1 = max(hiBin - 2, 0), b1 = min(hiBin + 2, NBINS - 1);
            if (b1 >= a1) {
                int s = s_pref[a1], e = s_pref[b1 + 1];
#pragma unroll 8
                for (int idx = s; idx < e; idx++)
                    cnt += (fabsf(s_sorted[idx] - g) <= DELTA_F) ? 1 : 0;
            }
        }

        float GD   = (float)cnt / DELTA_F;
        float beta = (float)N_ELEMS / (GD + EPS_F);
        float term = beta * loss;      // >= 0
        fixterm = (unsigned long long)((double)term * FIX_SCALE);
    }

    // ---- P4: deterministic finalize (u64 fixed-point; shuffle reduce) ----
    {
        unsigned long long v = fixterm;
#pragma unroll
        for (int off = 16; off > 0; off >>= 1)
            v += __shfl_down_sync(0xffffffffu, v, off);
        if ((t & 31) == 0) s_acc[t >> 5] = v;
        __syncthreads();
        if (t < 8) {
            unsigned long long w = s_acc[t];
#pragma unroll
            for (int off = 4; off > 0; off >>= 1)
                w += __shfl_down_sync(0xffu, w, off);
            if (t == 0) {
                atomicAdd(&d_accum, w);
                __threadfence();
                if (atomicAdd(&d_done, 1) == NCTA - 1) {
                    __threadfence();
                    unsigned long long total = atomicAdd(&d_accum, 0ULL);
                    out[0] = (float)(((double)total / FIX_SCALE) / (double)N_ELEMS);
                    d_accum = 0ULL;    // restore invariants for next replay
                    d_done  = 0;
                    __threadfence();
                }
            }
        }
    }
}

// ---------------------------------------------------------------------------
extern "C" void kernel_launch(void* const* d_in, const int* in_sizes, int n_in,
                              void* d_out, int out_size) {
    const float* logits  = (const float*)d_in[0];
    const float* targets = (const float*)d_in[1];
    float* out = (float*)d_out;

    cudaFuncSetAttribute(ghm_fused, cudaFuncAttributeMaxDynamicSharedMemorySize,
                         SMEM_TOTAL_BYTES);
    ghm_fused<<<NCTA, TPB, SMEM_TOTAL_BYTES>>>(logits, targets, out);
}